// round 9
// baseline (speedup 1.0000x reference)
#include <cuda_runtime.h>
#include <cstdint>
#include <math.h>

// ---------------------------------------------------------------- constants
#define NB   32
#define NS   2048
#define ND   768
#define NE   8
#define NH   256
#define TOK  (NB*NS)          // 65536
#define G3   (3*NH)           // 768

// output layout (float32, concatenated flattened tuple)
#define OUT_EW   0
#define OUT_IDX  (TOK*4)                // 262144
#define OUT_RW   (TOK*8)                // 524288
#define OUT_NH   (OUT_RW + TOK*8)       // 1048576
#define OUT_C    (OUT_NH + NB*NH)       // 1056768
#define OUT_LB   (OUT_C + TOK)          // 1122304
#define OUT_CR   (OUT_LB + 1)           // 1122305

// ---------------------------------------------------------------- scratch
__device__ float  g_gi[(size_t)TOK * G3];     // [B*S, 768]  ~201MB
__device__ float  g_g [(size_t)TOK * NH];     // [B*S, 256]  ~64MB
__device__ float  g_feats[(size_t)TOK * 256]; // heads gemm out ~64MB
__device__ float  g_Wcomb[256 * 256];
__device__ float  g_bcomb[256];
__device__ double g_acc[9];                   // 8 usage sums + complexity^2 sum

// ---------------------------------------------------------------- helpers
__device__ __forceinline__ unsigned long long dup2f(float x) {
    unsigned long long r;
    asm("mov.b64 %0, {%1, %1};" : "=l"(r) : "f"(x));
    return r;
}
__device__ __forceinline__ void fma2(unsigned long long& acc,
                                     unsigned long long a, unsigned long long b) {
    asm("fma.rn.f32x2 %0, %1, %2, %0;" : "+l"(acc) : "l"(a), "l"(b));
}
__device__ __forceinline__ float2 unpack2(unsigned long long v) {
    float2 f;
    asm("mov.b64 {%0, %1}, %2;" : "=f"(f.x), "=f"(f.y) : "l"(v));
    return f;
}
__device__ __forceinline__ uint32_t smem_u32(const void* p) {
    uint32_t a;
    asm("{ .reg .u64 t; cvta.to.shared.u64 t, %1; cvt.u32.u64 %0, t; }"
        : "=r"(a) : "l"(p));
    return a;
}
__device__ __forceinline__ void st_cluster_f32(uint32_t saddr, uint32_t rank, float v) {
    uint32_t r;
    asm volatile("mapa.shared::cluster.u32 %0, %1, %2;" : "=r"(r) : "r"(saddr), "r"(rank));
    asm volatile("st.shared::cluster.f32 [%0], %1;" :: "r"(r), "f"(v) : "memory");
}
__device__ __forceinline__ void cluster_sync_() {
    asm volatile("barrier.cluster.arrive.aligned;\n\tbarrier.cluster.wait.aligned;" ::: "memory");
}
__device__ __forceinline__ float sigmoidf_(float x) { return 1.f / (1.f + expf(-x)); }

// ============================================================== SGEMM (NT)
// C[m][n] = sum_k A[m][k]*B[n][k] + bias[n]
// BM=BN=128, BK=16, 256 threads, 8x8 per thread via f32x2.
// A tile stored PRE-DUPLICATED ({a,a} per entry) so the inner loop has no
// mov.b64 lane-duplication — pure fma2 + LDS.
__global__ __launch_bounds__(256, 2)
void sgemm_nt(const float* __restrict__ A, int lda,
              const float* __restrict__ B, int ldb,
              const float* __restrict__ bias,
              float* __restrict__ C, int ldc, int K)
{
    __shared__ unsigned long long As2[16 * 128];   // duplicated pairs, 16KB
    __shared__ float Bs[16 * 128];                 // 8KB

    const int tid = threadIdx.x;
    const int tx  = tid & 15, ty = tid >> 4;
    const int tx4 = tx * 4;
    const size_t bm = (size_t)blockIdx.y * 128;
    const size_t bn = (size_t)blockIdx.x * 128;

    const int r0 = tid >> 2;          // 0..63
    const int r1 = r0 + 64;
    const int c4 = (tid & 3) * 4;     // 0,4,8,12

    const float* Ag0 = A + (bm + r0) * (size_t)lda + c4;
    const float* Ag1 = A + (bm + r1) * (size_t)lda + c4;
    const float* Bg0 = B + (bn + r0) * (size_t)ldb + c4;
    const float* Bg1 = B + (bn + r1) * (size_t)ldb + c4;

    unsigned long long acc[8][4];
#pragma unroll
    for (int i = 0; i < 8; i++)
#pragma unroll
        for (int jp = 0; jp < 4; jp++) acc[i][jp] = 0ull;

    float4 pa0 = *(const float4*)Ag0;
    float4 pa1 = *(const float4*)Ag1;
    float4 pb0 = *(const float4*)Bg0;
    float4 pb1 = *(const float4*)Bg1;

    const int nk = K >> 4;
    for (int kt = 0; kt < nk; kt++) {
#pragma unroll
        for (int jj = 0; jj < 4; jj++) {
            As2[(c4 + jj) * 128 + r0] = dup2f(((const float*)&pa0)[jj]);
            As2[(c4 + jj) * 128 + r1] = dup2f(((const float*)&pa1)[jj]);
            Bs [(c4 + jj) * 128 + r0] = ((const float*)&pb0)[jj];
            Bs [(c4 + jj) * 128 + r1] = ((const float*)&pb1)[jj];
        }
        __syncthreads();

        if (kt + 1 < nk) {
            const int off = (kt + 1) * 16;
            pa0 = *(const float4*)(Ag0 + off);
            pa1 = *(const float4*)(Ag1 + off);
            pb0 = *(const float4*)(Bg0 + off);
            pb1 = *(const float4*)(Bg1 + off);
        }

#pragma unroll
        for (int k = 0; k < 16; k++) {
            const ulonglong2* a2 = (const ulonglong2*)(As2 + k * 128);
            ulonglong2 q0 = a2[ty * 2];          // dup(am0), dup(am1)
            ulonglong2 q1 = a2[ty * 2 + 1];      // dup(am2), dup(am3)
            ulonglong2 q2 = a2[32 + ty * 2];     // dup(am4), dup(am5)
            ulonglong2 q3 = a2[32 + ty * 2 + 1]; // dup(am6), dup(am7)
            const ulonglong2* bsr = (const ulonglong2*)(Bs + k * 128);
            ulonglong2 b0 = bsr[tx];
            ulonglong2 b1 = bsr[16 + tx];
            unsigned long long ad[8] = {q0.x, q0.y, q1.x, q1.y,
                                        q2.x, q2.y, q3.x, q3.y};
#pragma unroll
            for (int i = 0; i < 8; i++) {
                fma2(acc[i][0], ad[i], b0.x);
                fma2(acc[i][1], ad[i], b0.y);
                fma2(acc[i][2], ad[i], b1.x);
                fma2(acc[i][3], ad[i], b1.y);
            }
        }
        __syncthreads();
    }

    float4 bb0 = *(const float4*)(bias + bn + tx4);
    float4 bb1 = *(const float4*)(bias + bn + 64 + tx4);

    const int ty4 = ty * 4;
#pragma unroll
    for (int i = 0; i < 8; i++) {
        size_t m = bm + (size_t)((i < 4) ? (ty4 + i) : (64 + ty4 + (i - 4)));
        float2 p0 = unpack2(acc[i][0]);
        float2 p1 = unpack2(acc[i][1]);
        float2 p2 = unpack2(acc[i][2]);
        float2 p3 = unpack2(acc[i][3]);
        float4 o0 = make_float4(p0.x + bb0.x, p0.y + bb0.y, p1.x + bb0.z, p1.y + bb0.w);
        float4 o1 = make_float4(p2.x + bb1.x, p2.y + bb1.y, p3.x + bb1.z, p3.y + bb1.w);
        *(float4*)&C[m * (size_t)ldc + bn + tx4]      = o0;
        *(float4*)&C[m * (size_t)ldc + bn + 64 + tx4] = o1;
    }
}

// ============================================================== GRU scan
// Cluster of 4 CTAs per batch element. CTA `rank` owns hidden units
// [64*rank, 64*rank+64) -> 192 rows of W_hh.
// W_hh in REGISTERS (2 threads per row, 128 K-elems each),
// h double-buffered in smem, gi software-pipelined,
// SINGLE __syncthreads per step (gate threads sum the two K-halves
// directly from ps[] — no second barrier, no 192-thread reduce pass).
#define GRU_THREADS 384

__global__ void __cluster_dims__(4, 1, 1) __launch_bounds__(GRU_THREADS, 1)
gru_kernel(const float* __restrict__ W_hh, const float* __restrict__ b_hh,
           float* __restrict__ out_hidden)
{
    __shared__ float hb[2][256];            // double-buffered hidden state
    __shared__ float ps[GRU_THREADS];       // partial sums (half0 | half1)

    const int tid  = threadIdx.x;
    const int rank = blockIdx.x;            // 0..3
    const int b    = blockIdx.y;            // 0..31
    const int half = (tid >= 192) ? 1 : 0;  // K-half (warp-uniform)
    const int r    = tid - half * 192;      // row 0..191  (= g*64 + j)
    const int g    = r >> 6;
    const int j    = r & 63;
    const int u    = rank * 64 + tid;       // unit id (valid only for tid<64)

    // ---- W_hh row slice into registers: 128 floats = 32 x 16B
    ulonglong2 w[32];
    {
        const ulonglong2* src = (const ulonglong2*)
            (W_hh + ((size_t)(g * 256 + rank * 64 + j)) * 256 + half * 128);
#pragma unroll
        for (int i = 0; i < 32; i++) w[i] = src[i];
    }

    if (tid < 256) { hb[0][tid] = 0.f; hb[1][tid] = 0.f; }

    float bhr = 0.f, bhz = 0.f, bhn = 0.f;
    if (tid < 64) {
        bhr = b_hh[u]; bhz = b_hh[256 + u]; bhn = b_hh[512 + u];
    }
    __syncthreads();
    cluster_sync_();   // everyone's hb zeroed before any remote store

    const float* gi_base = g_gi + (size_t)b * NS * G3;
    float*       gout    = g_g  + (size_t)b * NS * NH;
    const uint32_t hb_u32 = smem_u32(&hb[0][0]);

    // gi software pipeline: current-step values in regs
    float cr = 0.f, cz = 0.f, cn = 0.f;
    if (tid < 64) { cr = gi_base[u]; cz = gi_base[256 + u]; cn = gi_base[512 + u]; }

    int p = 0;
#pragma unroll 1
    for (int t = 0; t < NS; t++) {
        // prefetch gi(t+1) — consumed a full step later, hides LDG latency
        float nr = 0.f, nz = 0.f, nn = 0.f;
        if (tid < 64 && t + 1 < NS) {
            const float* gn_ = gi_base + (size_t)(t + 1) * G3;
            nr = gn_[u]; nz = gn_[256 + u]; nn = gn_[512 + u];
        }

        // gemv: 128-MAC partial dot from register W, broadcast-LDS h
        const ulonglong2* hv = (const ulonglong2*)(&hb[p][half * 128]);
        unsigned long long a0 = 0ull, a1 = 0ull, a2 = 0ull, a3 = 0ull;
#pragma unroll
        for (int i = 0; i < 32; i += 2) {
            ulonglong2 h0 = hv[i], h1 = hv[i + 1];
            fma2(a0, w[i].x,     h0.x);
            fma2(a1, w[i].y,     h0.y);
            fma2(a2, w[i + 1].x, h1.x);
            fma2(a3, w[i + 1].y, h1.y);
        }
        float2 f0 = unpack2(a0), f1 = unpack2(a1), f2 = unpack2(a2), f3 = unpack2(a3);
        ps[tid] = ((f0.x + f0.y) + (f1.x + f1.y)) + ((f2.x + f2.y) + (f3.x + f3.y));
        __syncthreads();   // the ONLY intra-CTA barrier per step

        if (tid < 64) {
            float hr = ps[tid]       + ps[192 + tid];
            float hz = ps[64 + tid]  + ps[256 + tid];
            float hn = ps[128 + tid] + ps[320 + tid];
            float rr = sigmoidf_(cr + bhr + hr);
            float zz = sigmoidf_(cz + bhz + hz);
            float n2 = tanhf(cn + bhn + rr * hn);
            float hnew = (1.f - zz) * n2 + zz * hb[p][u];
            gout[(size_t)t * NH + u] = hnew;
            if (t == NS - 1) out_hidden[b * NH + u] = hnew;

            uint32_t dst = hb_u32 + (uint32_t)((((p ^ 1) * 256) + u) * 4);
#pragma unroll
            for (int c = 0; c < 4; c++)
                st_cluster_f32(dst, (uint32_t)c, hnew);   // h(t+1) to CTA c
        }
        // hardware cluster barrier: release/acquire orders the remote stores;
        // also protects ps[] from being overwritten before gates consumed it
        cluster_sync_();
        p ^= 1;
        cr = nr; cz = nz; cn = nn;
    }
    // no CTA exits while peers may still target its smem
    cluster_sync_();
}

// ============================================================== prep
__global__ void prep_kernel(const float* __restrict__ Wc1, const float* __restrict__ bc1,
                            const float* __restrict__ Wr,  const float* __restrict__ br,
                            const float* __restrict__ Wk1, const float* __restrict__ bk1)
{
    int r = blockIdx.x, c = threadIdx.x;
    float v = 0.f, bv = 0.f;
    if (r < 128)       { v = Wc1[r * 256 + c];         bv = bc1[r];       }
    else if (r < 136)  { v = Wr [(r - 128) * 256 + c]; bv = br [r - 128]; }
    else if (r < 200)  { v = Wk1[(r - 136) * 256 + c]; bv = bk1[r - 136]; }
    g_Wcomb[r * 256 + c] = v;
    if (c == 0) g_bcomb[r] = bv;
    if (r == 0 && c < 9) g_acc[c] = 0.0;
}

// ============================================================== router
__global__ __launch_bounds__(256)
void router_kernel(const float* __restrict__ Wc2, const float* __restrict__ bc2,
                   const float* __restrict__ Wk2, const float* __restrict__ bk2,
                   float* __restrict__ out)
{
    __shared__ double sacc[9];
    const int tid = threadIdx.x;
    if (tid < 9) sacc[tid] = 0.0;
    __syncthreads();

    const int warp = tid >> 5, lane = tid & 31;
    const int i = blockIdx.x * 8 + warp;           // token index
    const float* row = g_feats + (size_t)i * 256;

    float4 f = *(const float4*)(row + lane * 4);
    float4 w = *(const float4*)(Wc2 + lane * 4);
    float s = fmaxf(f.x, 0.f) * w.x + fmaxf(f.y, 0.f) * w.y +
              fmaxf(f.z, 0.f) * w.z + fmaxf(f.w, 0.f) * w.w;
    float2 f2 = *(const float2*)(row + 136 + lane * 2);
    float2 w2 = *(const float2*)(Wk2 + lane * 2);
    float s2 = fmaxf(f2.x, 0.f) * w2.x + fmaxf(f2.y, 0.f) * w2.y;
#pragma unroll
    for (int o = 16; o > 0; o >>= 1) {
        s  += __shfl_xor_sync(0xffffffffu, s,  o);
        s2 += __shfl_xor_sync(0xffffffffu, s2, o);
    }

    if (lane == 0) {
        float comp = sigmoidf_(s + bc2[0]);
        float tsc  = sigmoidf_(s2 + bk2[0]);

        float lg[NE];
        float mx = -1e30f;
#pragma unroll
        for (int e = 0; e < NE; e++) { lg[e] = row[128 + e]; mx = fmaxf(mx, lg[e]); }
        float sum = 0.f;
#pragma unroll
        for (int e = 0; e < NE; e++) { lg[e] = expf(lg[e] - mx); sum += lg[e]; }
        float inv = 1.f / sum;
        float rw[NE];
#pragma unroll
        for (int e = 0; e < NE; e++) {
            rw[e] = lg[e] * inv;
            out[OUT_RW + (size_t)i * NE + e] = rw[e];
        }

        int   idx[4];
        float tv[4];
        bool  used[NE] = {false, false, false, false, false, false, false, false};
#pragma unroll
        for (int s4 = 0; s4 < 4; s4++) {
            int best = 0; float bv = -1e30f;
#pragma unroll
            for (int e = 0; e < NE; e++)
                if (!used[e] && rw[e] > bv) { bv = rw[e]; best = e; }
            used[best] = true; tv[s4] = bv; idx[s4] = best;
        }

        float combined = 0.7f * comp + 0.3f * tsc;
        int kk = (int)rintf(1.f + combined * 3.f);
        if (kk < 1) kk = 1; if (kk > 4) kk = 4;

        float ms = 0.f, mw[4];
#pragma unroll
        for (int s4 = 0; s4 < 4; s4++) { mw[s4] = (s4 < kk) ? tv[s4] : 0.f; ms += mw[s4]; }
        if (!(ms > 0.f)) ms = 1.f;
        float im = 1.f / ms;
#pragma unroll
        for (int s4 = 0; s4 < 4; s4++) {
            out[OUT_EW  + (size_t)i * 4 + s4] = mw[s4] * im;
            out[OUT_IDX + (size_t)i * 4 + s4] = (float)idx[s4];
        }
        out[OUT_C + i] = comp;

#pragma unroll
        for (int e = 0; e < NE; e++) atomicAdd(&sacc[e], (double)rw[e]);
        atomicAdd(&sacc[8], (double)comp * (double)comp);
    }
    __syncthreads();
    if (tid < 9) atomicAdd(&g_acc[tid], sacc[tid]);
}

// ============================================================== finalize
__global__ void finalize_kernel(float* __restrict__ out)
{
    double s = 0.0;
#pragma unroll
    for (int e = 0; e < NE; e++) {
        double u = g_acc[e] / (double)TOK - 1.0 / (double)NE;
        s += u * u;
    }
    out[OUT_LB] = (float)(s / (double)NE * 0.01);
    out[OUT_CR] = (float)(g_acc[8] / (double)TOK * 0.001);
}

// ============================================================== launch
extern "C" void kernel_launch(void* const* d_in, const int* in_sizes, int n_in,
                              void* d_out, int out_size)
{
    (void)in_sizes; (void)n_in; (void)out_size;
    const float* x    = (const float*)d_in[0];
    // d_in[1] = layer_idx (unused)
    const float* W_ih = (const float*)d_in[2];   // [768, 776]
    const float* W_hh = (const float*)d_in[3];   // [768, 256]
    const float* b_ih = (const float*)d_in[4];
    const float* b_hh = (const float*)d_in[5];
    const float* Wc1  = (const float*)d_in[6];
    const float* bc1  = (const float*)d_in[7];
    const float* Wc2  = (const float*)d_in[8];
    const float* bc2  = (const float*)d_in[9];
    const float* Wr   = (const float*)d_in[10];
    const float* br   = (const float*)d_in[11];
    const float* Wk1  = (const float*)d_in[12];
    const float* bk1  = (const float*)d_in[13];
    const float* Wk2  = (const float*)d_in[14];
    const float* bk2  = (const float*)d_in[15];
    float* out = (float*)d_out;

    static float* p_gi = nullptr;
    static float* p_g = nullptr;
    static float* p_feats = nullptr;
    static float* p_wc = nullptr;
    static float* p_bc = nullptr;
    if (!p_gi) {
        cudaGetSymbolAddress((void**)&p_gi,    g_gi);
        cudaGetSymbolAddress((void**)&p_g,     g_g);
        cudaGetSymbolAddress((void**)&p_feats, g_feats);
        cudaGetSymbolAddress((void**)&p_wc,    g_Wcomb);
        cudaGetSymbolAddress((void**)&p_bc,    g_bcomb);
    }

    // 1. pack head weights + zero loss accumulators
    prep_kernel<<<256, 256>>>(Wc1, bc1, Wr, br, Wk1, bk1);

    // 2. gi = x @ W_ih[:, :768]^T + b_ih   (M=65536, N=768, K=768)
    sgemm_nt<<<dim3(G3 / 128, TOK / 128), 256>>>(x, ND, W_ih, ND + NE, b_ih,
                                                 p_gi, G3, ND);

    // 3. GRU scan (writes g_g and new_hidden)
    gru_kernel<<<dim3(4, NB), GRU_THREADS>>>(W_hh, b_hh, out + OUT_NH);

    // 4. heads: feats = g @ Wcomb^T + bcomb   (M=65536, N=256, K=256)
    sgemm_nt<<<dim3(256 / 128, TOK / 128), 256>>>(p_g, NH, p_wc, NH, p_bc,
                                                  p_feats, 256, NH);

    // 5. router epilogue
    router_kernel<<<TOK / 8, 256>>>(Wc2, bc2, Wk2, bk2, out);

    // 6. losses
    finalize_kernel<<<1, 1>>>(out);
}

// round 10
// speedup vs baseline: 1.0088x; 1.0088x over previous
#include <cuda_runtime.h>
#include <cstdint>
#include <math.h>

// ---------------------------------------------------------------- constants
#define NB   32
#define NS   2048
#define ND   768
#define NE   8
#define NH   256
#define TOK  (NB*NS)          // 65536
#define G3   (3*NH)           // 768

// output layout (float32, concatenated flattened tuple)
#define OUT_EW   0
#define OUT_IDX  (TOK*4)                // 262144
#define OUT_RW   (TOK*8)                // 524288
#define OUT_NH   (OUT_RW + TOK*8)       // 1048576
#define OUT_C    (OUT_NH + NB*NH)       // 1056768
#define OUT_LB   (OUT_C + TOK)          // 1122304
#define OUT_CR   (OUT_LB + 1)           // 1122305

// ---------------------------------------------------------------- scratch
__device__ float  g_gi[(size_t)TOK * G3];     // [B*S, 768]  ~201MB
__device__ float  g_g [(size_t)TOK * NH];     // [B*S, 256]  ~64MB
__device__ float  g_feats[(size_t)TOK * 256]; // heads gemm out ~64MB
__device__ float  g_Wcomb[256 * 256];
__device__ float  g_bcomb[256];
__device__ double g_acc[9];                   // 8 usage sums + complexity^2 sum

// ---------------------------------------------------------------- helpers
__device__ __forceinline__ unsigned long long dup2f(float x) {
    unsigned long long r;
    asm("mov.b64 %0, {%1, %1};" : "=l"(r) : "f"(x));
    return r;
}
__device__ __forceinline__ void fma2(unsigned long long& acc,
                                     unsigned long long a, unsigned long long b) {
    asm("fma.rn.f32x2 %0, %1, %2, %0;" : "+l"(acc) : "l"(a), "l"(b));
}
__device__ __forceinline__ float2 unpack2(unsigned long long v) {
    float2 f;
    asm("mov.b64 {%0, %1}, %2;" : "=f"(f.x), "=f"(f.y) : "l"(v));
    return f;
}
__device__ __forceinline__ uint32_t smem_u32(const void* p) {
    uint32_t a;
    asm("{ .reg .u64 t; cvta.to.shared.u64 t, %1; cvt.u32.u64 %0, t; }"
        : "=r"(a) : "l"(p));
    return a;
}
__device__ __forceinline__ void st_cluster_f32(uint32_t saddr, uint32_t rank, float v) {
    uint32_t r;
    asm volatile("mapa.shared::cluster.u32 %0, %1, %2;" : "=r"(r) : "r"(saddr), "r"(rank));
    asm volatile("st.shared::cluster.f32 [%0], %1;" :: "r"(r), "f"(v) : "memory");
}
__device__ __forceinline__ void cluster_sync_() {
    asm volatile("barrier.cluster.arrive.aligned;\n\tbarrier.cluster.wait.aligned;" ::: "memory");
}
__device__ __forceinline__ float sigmoidf_(float x) { return 1.f / (1.f + expf(-x)); }

// tf32 helpers
__device__ __forceinline__ float tf32r(float x) {
    uint32_t u;
    asm("cvt.rna.tf32.f32 %0, %1;" : "=r"(u) : "f"(x));
    return __uint_as_float(u);
}
__device__ __forceinline__ void mma_tf32(float* c, const uint32_t* a, const uint32_t* b) {
    asm volatile(
        "mma.sync.aligned.m16n8k8.row.col.f32.tf32.tf32.f32 "
        "{%0,%1,%2,%3}, {%4,%5,%6,%7}, {%8,%9}, {%0,%1,%2,%3};"
        : "+f"(c[0]), "+f"(c[1]), "+f"(c[2]), "+f"(c[3])
        : "r"(a[0]), "r"(a[1]), "r"(a[2]), "r"(a[3]), "r"(b[0]), "r"(b[1]));
}
// swizzled smem index: row stride 136 floats, XOR-8 swizzle keyed on k>>2.
// Conflict-free for the (k = 4*(tid&3)+jj, m = tid>>2) store pattern AND for
// all mma fragment load patterns (k>>2 is lane-constant there).
__device__ __forceinline__ int sidx(int k, int m) {
    return k * 136 + (m ^ ((k >> 2) << 3));
}

// ============================================================== GEMM-A: tf32x3 tensor-core
// C[m][n] = sum_k A[m][k]*B[n][k] + bias[n]
// BM=128, BN=128, BK=16. 256 threads = 8 warps (2m x 4n), warp tile 64x32.
// Each operand split x = hi + lo (tf32 each); 3 mma passes: Al*Bh, Ah*Bl, Ah*Bh.
__global__ __launch_bounds__(256, 2)
void gemm_tf32x3(const float* __restrict__ A, int lda,
                 const float* __restrict__ B, int ldb,
                 const float* __restrict__ bias,
                 float* __restrict__ C, int ldc, int K)
{
    __shared__ float Ah[16 * 136], Al[16 * 136];
    __shared__ float Bh[16 * 136], Bl[16 * 136];

    const int tid  = threadIdx.x;
    const int lane = tid & 31, warp = tid >> 5;
    const int wm = warp & 1;        // 0..1 -> 64 rows each
    const int wn = warp >> 1;       // 0..3 -> 32 cols each
    const int gid = lane >> 2, tig = lane & 3;

    const size_t bm = (size_t)blockIdx.y * 128;
    const size_t bn = (size_t)blockIdx.x * 128;

    const int r0 = tid >> 2;          // 0..63
    const int r1 = r0 + 64;
    const int c4 = (tid & 3) * 4;     // 0,4,8,12

    const float* Ag0 = A + (bm + r0) * (size_t)lda + c4;
    const float* Ag1 = A + (bm + r1) * (size_t)lda + c4;
    const float* Bg0 = B + (bn + r0) * (size_t)ldb + c4;
    const float* Bg1 = B + (bn + r1) * (size_t)ldb + c4;

    float acc[4][4][4];
#pragma unroll
    for (int mt = 0; mt < 4; mt++)
#pragma unroll
        for (int nt = 0; nt < 4; nt++)
#pragma unroll
            for (int i = 0; i < 4; i++) acc[mt][nt][i] = 0.f;

    float4 pa0 = *(const float4*)Ag0;
    float4 pa1 = *(const float4*)Ag1;
    float4 pb0 = *(const float4*)Bg0;
    float4 pb1 = *(const float4*)Bg1;

    const int nk = K >> 4;
    for (int kt = 0; kt < nk; kt++) {
#pragma unroll
        for (int jj = 0; jj < 4; jj++) {
            int k = c4 + jj;
            float va0 = ((const float*)&pa0)[jj];
            float va1 = ((const float*)&pa1)[jj];
            float vb0 = ((const float*)&pb0)[jj];
            float vb1 = ((const float*)&pb1)[jj];
            float h;
            h = tf32r(va0); Ah[sidx(k, r0)] = h; Al[sidx(k, r0)] = tf32r(va0 - h);
            h = tf32r(va1); Ah[sidx(k, r1)] = h; Al[sidx(k, r1)] = tf32r(va1 - h);
            h = tf32r(vb0); Bh[sidx(k, r0)] = h; Bl[sidx(k, r0)] = tf32r(vb0 - h);
            h = tf32r(vb1); Bh[sidx(k, r1)] = h; Bl[sidx(k, r1)] = tf32r(vb1 - h);
        }
        __syncthreads();

        if (kt + 1 < nk) {
            const int off = (kt + 1) * 16;
            pa0 = *(const float4*)(Ag0 + off);
            pa1 = *(const float4*)(Ag1 + off);
            pb0 = *(const float4*)(Bg0 + off);
            pb1 = *(const float4*)(Bg1 + off);
        }

#pragma unroll
        for (int k8 = 0; k8 < 16; k8 += 8) {
            // B fragments for 4 n-tiles (hoisted)
            uint32_t bh[4][2], bl[4][2];
#pragma unroll
            for (int nt = 0; nt < 4; nt++) {
                int n0 = wn * 32 + nt * 8 + gid;
                bh[nt][0] = __float_as_uint(Bh[sidx(k8 + tig,     n0)]);
                bh[nt][1] = __float_as_uint(Bh[sidx(k8 + tig + 4, n0)]);
                bl[nt][0] = __float_as_uint(Bl[sidx(k8 + tig,     n0)]);
                bl[nt][1] = __float_as_uint(Bl[sidx(k8 + tig + 4, n0)]);
            }
#pragma unroll
            for (int mt = 0; mt < 4; mt++) {
                int m0 = wm * 64 + mt * 16 + gid;
                uint32_t ah[4], al[4];
                ah[0] = __float_as_uint(Ah[sidx(k8 + tig,     m0)]);
                ah[1] = __float_as_uint(Ah[sidx(k8 + tig,     m0 + 8)]);
                ah[2] = __float_as_uint(Ah[sidx(k8 + tig + 4, m0)]);
                ah[3] = __float_as_uint(Ah[sidx(k8 + tig + 4, m0 + 8)]);
                al[0] = __float_as_uint(Al[sidx(k8 + tig,     m0)]);
                al[1] = __float_as_uint(Al[sidx(k8 + tig,     m0 + 8)]);
                al[2] = __float_as_uint(Al[sidx(k8 + tig + 4, m0)]);
                al[3] = __float_as_uint(Al[sidx(k8 + tig + 4, m0 + 8)]);
#pragma unroll
                for (int nt = 0; nt < 4; nt++) {
                    mma_tf32(acc[mt][nt], al, bh[nt]);
                    mma_tf32(acc[mt][nt], ah, bl[nt]);
                    mma_tf32(acc[mt][nt], ah, bh[nt]);
                }
            }
        }
        __syncthreads();
    }

    // epilogue: c0/c1 -> (row gid, col tig*2/+1); c2/c3 -> row gid+8
#pragma unroll
    for (int nt = 0; nt < 4; nt++) {
        size_t gcol = bn + wn * 32 + nt * 8 + tig * 2;
        float2 bs = *(const float2*)&bias[gcol];
#pragma unroll
        for (int mt = 0; mt < 4; mt++) {
            size_t row0 = bm + wm * 64 + mt * 16 + gid;
            float2 o0 = make_float2(acc[mt][nt][0] + bs.x, acc[mt][nt][1] + bs.y);
            float2 o1 = make_float2(acc[mt][nt][2] + bs.x, acc[mt][nt][3] + bs.y);
            *(float2*)&C[row0 * (size_t)ldc + gcol]       = o0;
            *(float2*)&C[(row0 + 8) * (size_t)ldc + gcol] = o1;
        }
    }
}

// ============================================================== SGEMM (NT) — round-8 version
// C[m][n] = sum_k A[m][k]*B[n][k] + bias[n]
// BM=BN=128, BK=16, 256 threads, 8x8 per thread via f32x2.
__global__ __launch_bounds__(256, 2)
void sgemm_nt(const float* __restrict__ A, int lda,
              const float* __restrict__ B, int ldb,
              const float* __restrict__ bias,
              float* __restrict__ C, int ldc, int K)
{
    __shared__ float As[16 * 128];
    __shared__ float Bs[16 * 128];

    const int tid = threadIdx.x;
    const int tx  = tid & 15, ty = tid >> 4;
    const int tx4 = tx * 4,  ty4 = ty * 4;
    const size_t bm = (size_t)blockIdx.y * 128;
    const size_t bn = (size_t)blockIdx.x * 128;

    const int r0 = tid >> 2;          // 0..63
    const int r1 = r0 + 64;
    const int c4 = (tid & 3) * 4;     // 0,4,8,12

    const float* Ag0 = A + (bm + r0) * (size_t)lda + c4;
    const float* Ag1 = A + (bm + r1) * (size_t)lda + c4;
    const float* Bg0 = B + (bn + r0) * (size_t)ldb + c4;
    const float* Bg1 = B + (bn + r1) * (size_t)ldb + c4;

    unsigned long long acc[8][4];
#pragma unroll
    for (int i = 0; i < 8; i++)
#pragma unroll
        for (int jp = 0; jp < 4; jp++) acc[i][jp] = 0ull;

    float4 pa0 = *(const float4*)Ag0;
    float4 pa1 = *(const float4*)Ag1;
    float4 pb0 = *(const float4*)Bg0;
    float4 pb1 = *(const float4*)Bg1;

    const int nk = K >> 4;
    for (int kt = 0; kt < nk; kt++) {
#pragma unroll
        for (int jj = 0; jj < 4; jj++) {
            As[(c4 + jj) * 128 + r0] = ((const float*)&pa0)[jj];
            As[(c4 + jj) * 128 + r1] = ((const float*)&pa1)[jj];
            Bs[(c4 + jj) * 128 + r0] = ((const float*)&pb0)[jj];
            Bs[(c4 + jj) * 128 + r1] = ((const float*)&pb1)[jj];
        }
        __syncthreads();

        if (kt + 1 < nk) {
            const int off = (kt + 1) * 16;
            pa0 = *(const float4*)(Ag0 + off);
            pa1 = *(const float4*)(Ag1 + off);
            pb0 = *(const float4*)(Bg0 + off);
            pb1 = *(const float4*)(Bg1 + off);
        }

#pragma unroll
        for (int k = 0; k < 16; k++) {
            const float* asr = As + k * 128;
            float4 a0 = *(const float4*)(asr + ty4);
            float4 a1 = *(const float4*)(asr + 64 + ty4);
            const ulonglong2* bsr = (const ulonglong2*)(Bs + k * 128);
            ulonglong2 b0 = bsr[tx];
            ulonglong2 b1 = bsr[16 + tx];
            float am[8] = {a0.x, a0.y, a0.z, a0.w, a1.x, a1.y, a1.z, a1.w};
#pragma unroll
            for (int i = 0; i < 8; i++) {
                unsigned long long ad = dup2f(am[i]);
                fma2(acc[i][0], ad, b0.x);
                fma2(acc[i][1], ad, b0.y);
                fma2(acc[i][2], ad, b1.x);
                fma2(acc[i][3], ad, b1.y);
            }
        }
        __syncthreads();
    }

    float4 bb0 = *(const float4*)(bias + bn + tx4);
    float4 bb1 = *(const float4*)(bias + bn + 64 + tx4);

#pragma unroll
    for (int i = 0; i < 8; i++) {
        size_t m = bm + (size_t)((i < 4) ? (ty4 + i) : (64 + ty4 + (i - 4)));
        float2 p0 = unpack2(acc[i][0]);
        float2 p1 = unpack2(acc[i][1]);
        float2 p2 = unpack2(acc[i][2]);
        float2 p3 = unpack2(acc[i][3]);
        float4 o0 = make_float4(p0.x + bb0.x, p0.y + bb0.y, p1.x + bb0.z, p1.y + bb0.w);
        float4 o1 = make_float4(p2.x + bb1.x, p2.y + bb1.y, p3.x + bb1.z, p3.y + bb1.w);
        *(float4*)&C[m * (size_t)ldc + bn + tx4]      = o0;
        *(float4*)&C[m * (size_t)ldc + bn + 64 + tx4] = o1;
    }
}

// ============================================================== GRU scan
// (unchanged from round 9: register-W, single intra-CTA barrier, cluster.sync)
#define GRU_THREADS 384

__global__ void __cluster_dims__(4, 1, 1) __launch_bounds__(GRU_THREADS, 1)
gru_kernel(const float* __restrict__ W_hh, const float* __restrict__ b_hh,
           float* __restrict__ out_hidden)
{
    __shared__ float hb[2][256];            // double-buffered hidden state
    __shared__ float ps[GRU_THREADS];       // partial sums (half0 | half1)

    const int tid  = threadIdx.x;
    const int rank = blockIdx.x;            // 0..3
    const int b    = blockIdx.y;            // 0..31
    const int half = (tid >= 192) ? 1 : 0;  // K-half (warp-uniform)
    const int r    = tid - half * 192;      // row 0..191  (= g*64 + j)
    const int g    = r >> 6;
    const int j    = r & 63;
    const int u    = rank * 64 + tid;       // unit id (valid only for tid<64)

    ulonglong2 w[32];
    {
        const ulonglong2* src = (const ulonglong2*)
            (W_hh + ((size_t)(g * 256 + rank * 64 + j)) * 256 + half * 128);
#pragma unroll
        for (int i = 0; i < 32; i++) w[i] = src[i];
    }

    if (tid < 256) { hb[0][tid] = 0.f; hb[1][tid] = 0.f; }

    float bhr = 0.f, bhz = 0.f, bhn = 0.f;
    if (tid < 64) {
        bhr = b_hh[u]; bhz = b_hh[256 + u]; bhn = b_hh[512 + u];
    }
    __syncthreads();
    cluster_sync_();

    const float* gi_base = g_gi + (size_t)b * NS * G3;
    float*       gout    = g_g  + (size_t)b * NS * NH;
    const uint32_t hb_u32 = smem_u32(&hb[0][0]);

    float cr = 0.f, cz = 0.f, cn = 0.f;
    if (tid < 64) { cr = gi_base[u]; cz = gi_base[256 + u]; cn = gi_base[512 + u]; }

    int p = 0;
#pragma unroll 1
    for (int t = 0; t < NS; t++) {
        float nr = 0.f, nz = 0.f, nn = 0.f;
        if (tid < 64 && t + 1 < NS) {
            const float* gn_ = gi_base + (size_t)(t + 1) * G3;
            nr = gn_[u]; nz = gn_[256 + u]; nn = gn_[512 + u];
        }

        const ulonglong2* hv = (const ulonglong2*)(&hb[p][half * 128]);
        unsigned long long a0 = 0ull, a1 = 0ull, a2 = 0ull, a3 = 0ull;
#pragma unroll
        for (int i = 0; i < 32; i += 2) {
            ulonglong2 h0 = hv[i], h1 = hv[i + 1];
            fma2(a0, w[i].x,     h0.x);
            fma2(a1, w[i].y,     h0.y);
            fma2(a2, w[i + 1].x, h1.x);
            fma2(a3, w[i + 1].y, h1.y);
        }
        float2 f0 = unpack2(a0), f1 = unpack2(a1), f2 = unpack2(a2), f3 = unpack2(a3);
        ps[tid] = ((f0.x + f0.y) + (f1.x + f1.y)) + ((f2.x + f2.y) + (f3.x + f3.y));
        __syncthreads();

        if (tid < 64) {
            float hr = ps[tid]       + ps[192 + tid];
            float hz = ps[64 + tid]  + ps[256 + tid];
            float hn = ps[128 + tid] + ps[320 + tid];
            float rr = sigmoidf_(cr + bhr + hr);
            float zz = sigmoidf_(cz + bhz + hz);
            float n2 = tanhf(cn + bhn + rr * hn);
            float hnew = (1.f - zz) * n2 + zz * hb[p][u];
            gout[(size_t)t * NH + u] = hnew;
            if (t == NS - 1) out_hidden[b * NH + u] = hnew;

            uint32_t dst = hb_u32 + (uint32_t)((((p ^ 1) * 256) + u) * 4);
#pragma unroll
            for (int c = 0; c < 4; c++)
                st_cluster_f32(dst, (uint32_t)c, hnew);
        }
        cluster_sync_();
        p ^= 1;
        cr = nr; cz = nz; cn = nn;
    }
    cluster_sync_();
}

// ============================================================== prep
__global__ void prep_kernel(const float* __restrict__ Wc1, const float* __restrict__ bc1,
                            const float* __restrict__ Wr,  const float* __restrict__ br,
                            const float* __restrict__ Wk1, const float* __restrict__ bk1)
{
    int r = blockIdx.x, c = threadIdx.x;
    float v = 0.f, bv = 0.f;
    if (r < 128)       { v = Wc1[r * 256 + c];         bv = bc1[r];       }
    else if (r < 136)  { v = Wr [(r - 128) * 256 + c]; bv = br [r - 128]; }
    else if (r < 200)  { v = Wk1[(r - 136) * 256 + c]; bv = bk1[r - 136]; }
    g_Wcomb[r * 256 + c] = v;
    if (c == 0) g_bcomb[r] = bv;
    if (r == 0 && c < 9) g_acc[c] = 0.0;
}

// ============================================================== router
__global__ __launch_bounds__(256)
void router_kernel(const float* __restrict__ Wc2, const float* __restrict__ bc2,
                   const float* __restrict__ Wk2, const float* __restrict__ bk2,
                   float* __restrict__ out)
{
    __shared__ double sacc[9];
    const int tid = threadIdx.x;
    if (tid < 9) sacc[tid] = 0.0;
    __syncthreads();

    const int warp = tid >> 5, lane = tid & 31;
    const int i = blockIdx.x * 8 + warp;           // token index
    const float* row = g_feats + (size_t)i * 256;

    float4 f = *(const float4*)(row + lane * 4);
    float4 w = *(const float4*)(Wc2 + lane * 4);
    float s = fmaxf(f.x, 0.f) * w.x + fmaxf(f.y, 0.f) * w.y +
              fmaxf(f.z, 0.f) * w.z + fmaxf(f.w, 0.f) * w.w;
    float2 f2 = *(const float2*)(row + 136 + lane * 2);
    float2 w2 = *(const float2*)(Wk2 + lane * 2);
    float s2 = fmaxf(f2.x, 0.f) * w2.x + fmaxf(f2.y, 0.f) * w2.y;
#pragma unroll
    for (int o = 16; o > 0; o >>= 1) {
        s  += __shfl_xor_sync(0xffffffffu, s,  o);
        s2 += __shfl_xor_sync(0xffffffffu, s2, o);
    }

    if (lane == 0) {
        float comp = sigmoidf_(s + bc2[0]);
        float tsc  = sigmoidf_(s2 + bk2[0]);

        float lg[NE];
        float mx = -1e30f;
#pragma unroll
        for (int e = 0; e < NE; e++) { lg[e] = row[128 + e]; mx = fmaxf(mx, lg[e]); }
        float sum = 0.f;
#pragma unroll
        for (int e = 0; e < NE; e++) { lg[e] = expf(lg[e] - mx); sum += lg[e]; }
        float inv = 1.f / sum;
        float rw[NE];
#pragma unroll
        for (int e = 0; e < NE; e++) {
            rw[e] = lg[e] * inv;
            out[OUT_RW + (size_t)i * NE + e] = rw[e];
        }

        int   idx[4];
        float tv[4];
        bool  used[NE] = {false, false, false, false, false, false, false, false};
#pragma unroll
        for (int s4 = 0; s4 < 4; s4++) {
            int best = 0; float bv = -1e30f;
#pragma unroll
            for (int e = 0; e < NE; e++)
                if (!used[e] && rw[e] > bv) { bv = rw[e]; best = e; }
            used[best] = true; tv[s4] = bv; idx[s4] = best;
        }

        float combined = 0.7f * comp + 0.3f * tsc;
        int kk = (int)rintf(1.f + combined * 3.f);
        if (kk < 1) kk = 1; if (kk > 4) kk = 4;

        float ms = 0.f, mw[4];
#pragma unroll
        for (int s4 = 0; s4 < 4; s4++) { mw[s4] = (s4 < kk) ? tv[s4] : 0.f; ms += mw[s4]; }
        if (!(ms > 0.f)) ms = 1.f;
        float im = 1.f / ms;
#pragma unroll
        for (int s4 = 0; s4 < 4; s4++) {
            out[OUT_EW  + (size_t)i * 4 + s4] = mw[s4] * im;
            out[OUT_IDX + (size_t)i * 4 + s4] = (float)idx[s4];
        }
        out[OUT_C + i] = comp;

#pragma unroll
        for (int e = 0; e < NE; e++) atomicAdd(&sacc[e], (double)rw[e]);
        atomicAdd(&sacc[8], (double)comp * (double)comp);
    }
    __syncthreads();
    if (tid < 9) atomicAdd(&g_acc[tid], sacc[tid]);
}

// ============================================================== finalize
__global__ void finalize_kernel(float* __restrict__ out)
{
    double s = 0.0;
#pragma unroll
    for (int e = 0; e < NE; e++) {
        double u = g_acc[e] / (double)TOK - 1.0 / (double)NE;
        s += u * u;
    }
    out[OUT_LB] = (float)(s / (double)NE * 0.01);
    out[OUT_CR] = (float)(g_acc[8] / (double)TOK * 0.001);
}

// ============================================================== launch
extern "C" void kernel_launch(void* const* d_in, const int* in_sizes, int n_in,
                              void* d_out, int out_size)
{
    (void)in_sizes; (void)n_in; (void)out_size;
    const float* x    = (const float*)d_in[0];
    // d_in[1] = layer_idx (unused)
    const float* W_ih = (const float*)d_in[2];   // [768, 776]
    const float* W_hh = (const float*)d_in[3];   // [768, 256]
    const float* b_ih = (const float*)d_in[4];
    const float* b_hh = (const float*)d_in[5];
    const float* Wc1  = (const float*)d_in[6];
    const float* bc1  = (const float*)d_in[7];
    const float* Wc2  = (const float*)d_in[8];
    const float* bc2  = (const float*)d_in[9];
    const float* Wr   = (const float*)d_in[10];
    const float* br   = (const float*)d_in[11];
    const float* Wk1  = (const float*)d_in[12];
    const float* bk1  = (const float*)d_in[13];
    const float* Wk2  = (const float*)d_in[14];
    const float* bk2  = (const float*)d_in[15];
    float* out = (float*)d_out;

    static float* p_gi = nullptr;
    static float* p_g = nullptr;
    static float* p_feats = nullptr;
    static float* p_wc = nullptr;
    static float* p_bc = nullptr;
    if (!p_gi) {
        cudaGetSymbolAddress((void**)&p_gi,    g_gi);
        cudaGetSymbolAddress((void**)&p_g,     g_g);
        cudaGetSymbolAddress((void**)&p_feats, g_feats);
        cudaGetSymbolAddress((void**)&p_wc,    g_Wcomb);
        cudaGetSymbolAddress((void**)&p_bc,    g_bcomb);
    }

    // 1. pack head weights + zero loss accumulators
    prep_kernel<<<256, 256>>>(Wc1, bc1, Wr, br, Wk1, bk1);

    // 2. gi = x @ W_ih[:, :768]^T + b_ih   (M=65536, N=768, K=768) — tf32x3 tensor cores
    gemm_tf32x3<<<dim3(G3 / 128, TOK / 128), 256>>>(x, ND, W_ih, ND + NE, b_ih,
                                                    p_gi, G3, ND);

    // 3. GRU scan (writes g_g and new_hidden)
    gru_kernel<<<dim3(4, NB), GRU_THREADS>>>(W_hh, b_hh, out + OUT_NH);

    // 4. heads: feats = g @ Wcomb^T + bcomb   (M=65536, N=256, K=256) — fp32 (round-8)
    sgemm_nt<<<dim3(256 / 128, TOK / 128), 256>>>(p_g, NH, p_wc, NH, p_bc,
                                                  p_feats, 256, NH);

    // 5. router epilogue
    router_kernel<<<TOK / 8, 256>>>(Wc2, bc2, Wk2, bk2, out);

    // 6. losses
    finalize_kernel<<<1, 1>>>(out);
}

// round 11
// speedup vs baseline: 1.1357x; 1.1258x over previous
#include <cuda_runtime.h>
#include <cstdint>
#include <math.h>

// ---------------------------------------------------------------- constants
#define NB   32
#define NS   2048
#define ND   768
#define NE   8
#define NH   256
#define TOK  (NB*NS)          // 65536
#define G3   (3*NH)           // 768

// output layout (float32, concatenated flattened tuple)
#define OUT_EW   0
#define OUT_IDX  (TOK*4)                // 262144
#define OUT_RW   (TOK*8)                // 524288
#define OUT_NH   (OUT_RW + TOK*8)       // 1048576
#define OUT_C    (OUT_NH + NB*NH)       // 1056768
#define OUT_LB   (OUT_C + TOK)          // 1122304
#define OUT_CR   (OUT_LB + 1)           // 1122305

// ---------------------------------------------------------------- scratch
__device__ float  g_gi[(size_t)TOK * G3];     // [B*S, 768]
__device__ float  g_g [(size_t)TOK * NH];     // [B*S, 256]
__device__ float  g_feats[(size_t)TOK * 256]; // heads gemm out
__device__ float  g_Wcomb[256 * 256];
__device__ float  g_bcomb[256];
__device__ double g_acc[9];                   // 8 usage sums + complexity^2 sum

// ---------------------------------------------------------------- helpers
__device__ __forceinline__ unsigned long long dup2f(float x) {
    unsigned long long r;
    asm("mov.b64 %0, {%1, %1};" : "=l"(r) : "f"(x));
    return r;
}
__device__ __forceinline__ void fma2(unsigned long long& acc,
                                     unsigned long long a, unsigned long long b) {
    asm("fma.rn.f32x2 %0, %1, %2, %0;" : "+l"(acc) : "l"(a), "l"(b));
}
__device__ __forceinline__ float2 unpack2(unsigned long long v) {
    float2 f;
    asm("mov.b64 {%0, %1}, %2;" : "=f"(f.x), "=f"(f.y) : "l"(v));
    return f;
}
__device__ __forceinline__ uint32_t smem_u32(const void* p) {
    uint32_t a;
    asm("{ .reg .u64 t; cvta.to.shared.u64 t, %1; cvt.u32.u64 %0, t; }"
        : "=r"(a) : "l"(p));
    return a;
}
__device__ __forceinline__ void st_cluster_f32(uint32_t saddr, uint32_t rank, float v) {
    uint32_t r;
    asm volatile("mapa.shared::cluster.u32 %0, %1, %2;" : "=r"(r) : "r"(saddr), "r"(rank));
    asm volatile("st.shared::cluster.f32 [%0], %1;" :: "r"(r), "f"(v) : "memory");
}
__device__ __forceinline__ void cluster_arrive_() {
    asm volatile("barrier.cluster.arrive.aligned;" ::: "memory");
}
__device__ __forceinline__ void cluster_wait_() {
    asm volatile("barrier.cluster.wait.aligned;" ::: "memory");
}
__device__ __forceinline__ void cluster_sync_() {
    cluster_arrive_(); cluster_wait_();
}
// fast gate math: MUFU-based, ~1e-7 rel error (same class as fp32 noise)
__device__ __forceinline__ float fast_sigmoid(float x) {
    return __fdividef(1.f, 1.f + __expf(-x));
}
__device__ __forceinline__ float fast_tanh(float x) {
    return 1.f - __fdividef(2.f, __expf(2.f * x) + 1.f);
}

// ============================================================== SGEMM (NT) — round-8 proven
// C[m][n] = sum_k A[m][k]*B[n][k] + bias[n]
// BM=BN=128, BK=16, 256 threads, 8x8 per thread via f32x2.
__global__ __launch_bounds__(256, 2)
void sgemm_nt(const float* __restrict__ A, int lda,
              const float* __restrict__ B, int ldb,
              const float* __restrict__ bias,
              float* __restrict__ C, int ldc, int K)
{
    __shared__ float As[16 * 128];
    __shared__ float Bs[16 * 128];

    const int tid = threadIdx.x;
    const int tx  = tid & 15, ty = tid >> 4;
    const int tx4 = tx * 4,  ty4 = ty * 4;
    const size_t bm = (size_t)blockIdx.y * 128;
    const size_t bn = (size_t)blockIdx.x * 128;

    const int r0 = tid >> 2;          // 0..63
    const int r1 = r0 + 64;
    const int c4 = (tid & 3) * 4;     // 0,4,8,12

    const float* Ag0 = A + (bm + r0) * (size_t)lda + c4;
    const float* Ag1 = A + (bm + r1) * (size_t)lda + c4;
    const float* Bg0 = B + (bn + r0) * (size_t)ldb + c4;
    const float* Bg1 = B + (bn + r1) * (size_t)ldb + c4;

    unsigned long long acc[8][4];
#pragma unroll
    for (int i = 0; i < 8; i++)
#pragma unroll
        for (int jp = 0; jp < 4; jp++) acc[i][jp] = 0ull;

    float4 pa0 = *(const float4*)Ag0;
    float4 pa1 = *(const float4*)Ag1;
    float4 pb0 = *(const float4*)Bg0;
    float4 pb1 = *(const float4*)Bg1;

    const int nk = K >> 4;
    for (int kt = 0; kt < nk; kt++) {
#pragma unroll
        for (int jj = 0; jj < 4; jj++) {
            As[(c4 + jj) * 128 + r0] = ((const float*)&pa0)[jj];
            As[(c4 + jj) * 128 + r1] = ((const float*)&pa1)[jj];
            Bs[(c4 + jj) * 128 + r0] = ((const float*)&pb0)[jj];
            Bs[(c4 + jj) * 128 + r1] = ((const float*)&pb1)[jj];
        }
        __syncthreads();

        if (kt + 1 < nk) {
            const int off = (kt + 1) * 16;
            pa0 = *(const float4*)(Ag0 + off);
            pa1 = *(const float4*)(Ag1 + off);
            pb0 = *(const float4*)(Bg0 + off);
            pb1 = *(const float4*)(Bg1 + off);
        }

#pragma unroll
        for (int k = 0; k < 16; k++) {
            const float* asr = As + k * 128;
            float4 a0 = *(const float4*)(asr + ty4);
            float4 a1 = *(const float4*)(asr + 64 + ty4);
            const ulonglong2* bsr = (const ulonglong2*)(Bs + k * 128);
            ulonglong2 b0 = bsr[tx];
            ulonglong2 b1 = bsr[16 + tx];
            float am[8] = {a0.x, a0.y, a0.z, a0.w, a1.x, a1.y, a1.z, a1.w};
#pragma unroll
            for (int i = 0; i < 8; i++) {
                unsigned long long ad = dup2f(am[i]);
                fma2(acc[i][0], ad, b0.x);
                fma2(acc[i][1], ad, b0.y);
                fma2(acc[i][2], ad, b1.x);
                fma2(acc[i][3], ad, b1.y);
            }
        }
        __syncthreads();
    }

    float4 bb0 = *(const float4*)(bias + bn + tx4);
    float4 bb1 = *(const float4*)(bias + bn + 64 + tx4);

#pragma unroll
    for (int i = 0; i < 8; i++) {
        size_t m = bm + (size_t)((i < 4) ? (ty4 + i) : (64 + ty4 + (i - 4)));
        float2 p0 = unpack2(acc[i][0]);
        float2 p1 = unpack2(acc[i][1]);
        float2 p2 = unpack2(acc[i][2]);
        float2 p3 = unpack2(acc[i][3]);
        float4 o0 = make_float4(p0.x + bb0.x, p0.y + bb0.y, p1.x + bb0.z, p1.y + bb0.w);
        float4 o1 = make_float4(p2.x + bb1.x, p2.y + bb1.y, p3.x + bb1.z, p3.y + bb1.w);
        *(float4*)&C[m * (size_t)ldc + bn + tx4]      = o0;
        *(float4*)&C[m * (size_t)ldc + bn + 64 + tx4] = o1;
    }
}

// ============================================================== GRU scan
// Register-resident W_hh, single intra-CTA barrier, cluster.sync handshake,
// fast-intrinsic gates, hold-load hoisted, gout STG inside barrier-wait shadow.
#define GRU_THREADS 384

__global__ void __cluster_dims__(4, 1, 1) __launch_bounds__(GRU_THREADS, 1)
gru_kernel(const float* __restrict__ W_hh, const float* __restrict__ b_hh,
           float* __restrict__ out_hidden)
{
    __shared__ float hb[2][256];            // double-buffered hidden state
    __shared__ float ps[GRU_THREADS];       // partial sums (half0 | half1)

    const int tid  = threadIdx.x;
    const int rank = blockIdx.x;            // 0..3
    const int b    = blockIdx.y;            // 0..31
    const int half = (tid >= 192) ? 1 : 0;  // K-half (warp-uniform)
    const int r    = tid - half * 192;      // row 0..191  (= g*64 + j)
    const int g    = r >> 6;
    const int j    = r & 63;
    const int u    = rank * 64 + tid;       // unit id (valid only for tid<64)

    ulonglong2 w[32];
    {
        const ulonglong2* src = (const ulonglong2*)
            (W_hh + ((size_t)(g * 256 + rank * 64 + j)) * 256 + half * 128);
#pragma unroll
        for (int i = 0; i < 32; i++) w[i] = src[i];
    }

    if (tid < 256) { hb[0][tid] = 0.f; hb[1][tid] = 0.f; }

    float bhr = 0.f, bhz = 0.f, bhn = 0.f;
    if (tid < 64) {
        bhr = b_hh[u]; bhz = b_hh[256 + u]; bhn = b_hh[512 + u];
    }
    __syncthreads();
    cluster_sync_();

    const float* gi_base = g_gi + (size_t)b * NS * G3;
    float*       gout    = g_g  + (size_t)b * NS * NH;
    const uint32_t hb_u32 = smem_u32(&hb[0][0]);

    float cr = 0.f, cz = 0.f, cn = 0.f;
    if (tid < 64) { cr = gi_base[u]; cz = gi_base[256 + u]; cn = gi_base[512 + u]; }

    int p = 0;
#pragma unroll 1
    for (int t = 0; t < NS; t++) {
        // prefetch gi(t+1) — consumed a full step later, hides LDG latency
        float nr = 0.f, nz = 0.f, nn = 0.f;
        if (tid < 64 && t + 1 < NS) {
            const float* gn_ = gi_base + (size_t)(t + 1) * G3;
            nr = gn_[u]; nz = gn_[256 + u]; nn = gn_[512 + u];
        }

        // gemv: 128-MAC partial dot from register W, broadcast-LDS h
        const ulonglong2* hv = (const ulonglong2*)(&hb[p][half * 128]);
        unsigned long long a0 = 0ull, a1 = 0ull, a2 = 0ull, a3 = 0ull;
#pragma unroll
        for (int i = 0; i < 32; i += 2) {
            ulonglong2 h0 = hv[i], h1 = hv[i + 1];
            fma2(a0, w[i].x,     h0.x);
            fma2(a1, w[i].y,     h0.y);
            fma2(a2, w[i + 1].x, h1.x);
            fma2(a3, w[i + 1].y, h1.y);
        }
        float2 f0 = unpack2(a0), f1 = unpack2(a1), f2 = unpack2(a2), f3 = unpack2(a3);
        ps[tid] = ((f0.x + f0.y) + (f1.x + f1.y)) + ((f2.x + f2.y) + (f3.x + f3.y));
        __syncthreads();   // the ONLY intra-CTA barrier per step

        float hnew = 0.f;
        if (tid < 64) {
            float hold = hb[p][u];                 // hoisted: overlap LDS latency
            float hr = ps[tid]       + ps[192 + tid];
            float hz = ps[64 + tid]  + ps[256 + tid];
            float hn = ps[128 + tid] + ps[320 + tid];
            float rr = fast_sigmoid(cr + bhr + hr);
            float zz = fast_sigmoid(cz + bhz + hz);
            float n2 = fast_tanh(cn + bhn + rr * hn);
            hnew = (1.f - zz) * n2 + zz * hold;

            uint32_t dst = hb_u32 + (uint32_t)((((p ^ 1) * 256) + u) * 4);
#pragma unroll
            for (int c = 0; c < 4; c++)
                st_cluster_f32(dst, (uint32_t)c, hnew);   // h(t+1) to CTA c
        }
        // split barrier: arrive (release covers remote stores), then do the
        // global-memory writes inside the wait shadow, then wait.
        cluster_arrive_();
        if (tid < 64) {
            gout[(size_t)t * NH + u] = hnew;
            if (t == NS - 1) out_hidden[b * NH + u] = hnew;
        }
        cluster_wait_();
        p ^= 1;
        cr = nr; cz = nz; cn = nn;
    }
    cluster_sync_();
}

// ============================================================== prep
__global__ void prep_kernel(const float* __restrict__ Wc1, const float* __restrict__ bc1,
                            const float* __restrict__ Wr,  const float* __restrict__ br,
                            const float* __restrict__ Wk1, const float* __restrict__ bk1)
{
    int r = blockIdx.x, c = threadIdx.x;
    float v = 0.f, bv = 0.f;
    if (r < 128)       { v = Wc1[r * 256 + c];         bv = bc1[r];       }
    else if (r < 136)  { v = Wr [(r - 128) * 256 + c]; bv = br [r - 128]; }
    else if (r < 200)  { v = Wk1[(r - 136) * 256 + c]; bv = bk1[r - 136]; }
    g_Wcomb[r * 256 + c] = v;
    if (c == 0) g_bcomb[r] = bv;
    if (r == 0 && c < 9) g_acc[c] = 0.0;
}

// ============================================================== router
__global__ __launch_bounds__(256)
void router_kernel(const float* __restrict__ Wc2, const float* __restrict__ bc2,
                   const float* __restrict__ Wk2, const float* __restrict__ bk2,
                   float* __restrict__ out)
{
    __shared__ double sacc[9];
    const int tid = threadIdx.x;
    if (tid < 9) sacc[tid] = 0.0;
    __syncthreads();

    const int warp = tid >> 5, lane = tid & 31;
    const int i = blockIdx.x * 8 + warp;           // token index
    const float* row = g_feats + (size_t)i * 256;

    float4 f = *(const float4*)(row + lane * 4);
    float4 w = *(const float4*)(Wc2 + lane * 4);
    float s = fmaxf(f.x, 0.f) * w.x + fmaxf(f.y, 0.f) * w.y +
              fmaxf(f.z, 0.f) * w.z + fmaxf(f.w, 0.f) * w.w;
    float2 f2 = *(const float2*)(row + 136 + lane * 2);
    float2 w2 = *(const float2*)(Wk2 + lane * 2);
    float s2 = fmaxf(f2.x, 0.f) * w2.x + fmaxf(f2.y, 0.f) * w2.y;
#pragma unroll
    for (int o = 16; o > 0; o >>= 1) {
        s  += __shfl_xor_sync(0xffffffffu, s,  o);
        s2 += __shfl_xor_sync(0xffffffffu, s2, o);
    }

    if (lane == 0) {
        // keep precise expf here: router outputs are directly compared
        float comp = 1.f / (1.f + expf(-(s + bc2[0])));
        float tsc  = 1.f / (1.f + expf(-(s2 + bk2[0])));

        float lg[NE];
        float mx = -1e30f;
#pragma unroll
        for (int e = 0; e < NE; e++) { lg[e] = row[128 + e]; mx = fmaxf(mx, lg[e]); }
        float sum = 0.f;
#pragma unroll
        for (int e = 0; e < NE; e++) { lg[e] = expf(lg[e] - mx); sum += lg[e]; }
        float inv = 1.f / sum;
        float rw[NE];
#pragma unroll
        for (int e = 0; e < NE; e++) {
            rw[e] = lg[e] * inv;
            out[OUT_RW + (size_t)i * NE + e] = rw[e];
        }

        int   idx[4];
        float tv[4];
        bool  used[NE] = {false, false, false, false, false, false, false, false};
#pragma unroll
        for (int s4 = 0; s4 < 4; s4++) {
            int best = 0; float bv = -1e30f;
#pragma unroll
            for (int e = 0; e < NE; e++)
                if (!used[e] && rw[e] > bv) { bv = rw[e]; best = e; }
            used[best] = true; tv[s4] = bv; idx[s4] = best;
        }

        float combined = 0.7f * comp + 0.3f * tsc;
        int kk = (int)rintf(1.f + combined * 3.f);
        if (kk < 1) kk = 1; if (kk > 4) kk = 4;

        float ms = 0.f, mw[4];
#pragma unroll
        for (int s4 = 0; s4 < 4; s4++) { mw[s4] = (s4 < kk) ? tv[s4] : 0.f; ms += mw[s4]; }
        if (!(ms > 0.f)) ms = 1.f;
        float im = 1.f / ms;
#pragma unroll
        for (int s4 = 0; s4 < 4; s4++) {
            out[OUT_EW  + (size_t)i * 4 + s4] = mw[s4] * im;
            out[OUT_IDX + (size_t)i * 4 + s4] = (float)idx[s4];
        }
        out[OUT_C + i] = comp;

#pragma unroll
        for (int e = 0; e < NE; e++) atomicAdd(&sacc[e], (double)rw[e]);
        atomicAdd(&sacc[8], (double)comp * (double)comp);
    }
    __syncthreads();
    if (tid < 9) atomicAdd(&g_acc[tid], sacc[tid]);
}

// ============================================================== finalize
__global__ void finalize_kernel(float* __restrict__ out)
{
    double s = 0.0;
#pragma unroll
    for (int e = 0; e < NE; e++) {
        double u = g_acc[e] / (double)TOK - 1.0 / (double)NE;
        s += u * u;
    }
    out[OUT_LB] = (float)(s / (double)NE * 0.01);
    out[OUT_CR] = (float)(g_acc[8] / (double)TOK * 0.001);
}

// ============================================================== launch
extern "C" void kernel_launch(void* const* d_in, const int* in_sizes, int n_in,
                              void* d_out, int out_size)
{
    (void)in_sizes; (void)n_in; (void)out_size;
    const float* x    = (const float*)d_in[0];
    // d_in[1] = layer_idx (unused)
    const float* W_ih = (const float*)d_in[2];   // [768, 776]
    const float* W_hh = (const float*)d_in[3];   // [768, 256]
    const float* b_ih = (const float*)d_in[4];
    const float* b_hh = (const float*)d_in[5];
    const float* Wc1  = (const float*)d_in[6];
    const float* bc1  = (const float*)d_in[7];
    const float* Wc2  = (const float*)d_in[8];
    const float* bc2  = (const float*)d_in[9];
    const float* Wr   = (const float*)d_in[10];
    const float* br   = (const float*)d_in[11];
    const float* Wk1  = (const float*)d_in[12];
    const float* bk1  = (const float*)d_in[13];
    const float* Wk2  = (const float*)d_in[14];
    const float* bk2  = (const float*)d_in[15];
    float* out = (float*)d_out;

    static float* p_gi = nullptr;
    static float* p_g = nullptr;
    static float* p_feats = nullptr;
    static float* p_wc = nullptr;
    static float* p_bc = nullptr;
    if (!p_gi) {
        cudaGetSymbolAddress((void**)&p_gi,    g_gi);
        cudaGetSymbolAddress((void**)&p_g,     g_g);
        cudaGetSymbolAddress((void**)&p_feats, g_feats);
        cudaGetSymbolAddress((void**)&p_wc,    g_Wcomb);
        cudaGetSymbolAddress((void**)&p_bc,    g_bcomb);
    }

    // 1. pack head weights + zero loss accumulators
    prep_kernel<<<256, 256>>>(Wc1, bc1, Wr, br, Wk1, bk1);

    // 2. gi = x @ W_ih[:, :768]^T + b_ih   (M=65536, N=768, K=768) — fp32 f32x2
    sgemm_nt<<<dim3(G3 / 128, TOK / 128), 256>>>(x, ND, W_ih, ND + NE, b_ih,
                                                 p_gi, G3, ND);

    // 3. GRU scan (writes g_g and new_hidden)
    gru_kernel<<<dim3(4, NB), GRU_THREADS>>>(W_hh, b_hh, out + OUT_NH);

    // 4. heads: feats = g @ Wcomb^T + bcomb   (M=65536, N=256, K=256)
    sgemm_nt<<<dim3(256 / 128, TOK / 128), 256>>>(p_g, NH, p_wc, NH, p_bc,
                                                  p_feats, 256, NH);

    // 5. router epilogue
    router_kernel<<<TOK / 8, 256>>>(Wc2, bc2, Wk2, bk2, out);

    // 6. losses
    finalize_kernel<<<1, 1>>>(out);
}